// round 14
// baseline (speedup 1.0000x reference)
#include <cuda_runtime.h>
#include <stdint.h>
#include <math.h>

// ---------------------------------------------------------------------------
// Permutation jax.random.permutation(key(42), 1024)[:256] — evaluated at
// COMPILE TIME (constexpr threefry2x32 + stable shell sort), baked into a
// __device__ const global table, read via vectorized LDG (global->L1).
// g_tab.v[col] = sample slot (0..255) or -1, packed int16 (2KB).
// ---------------------------------------------------------------------------

struct __align__(16) PermTab { short v[1024]; };

constexpr uint32_t rotl32c(uint32_t x, int r) {
    return (x << r) | (x >> (32 - r));
}

constexpr void tfryc(uint32_t k0, uint32_t k1, uint32_t c0, uint32_t c1,
                     uint32_t& o0, uint32_t& o1) {
    uint32_t ks2 = k0 ^ k1 ^ 0x1BD11BDAu;
    uint32_t x0 = c0 + k0;
    uint32_t x1 = c1 + k1;
#define TF_G(r0, r1, r2, r3)                          \
    x0 += x1; x1 = rotl32c(x1, r0); x1 ^= x0;         \
    x0 += x1; x1 = rotl32c(x1, r1); x1 ^= x0;         \
    x0 += x1; x1 = rotl32c(x1, r2); x1 ^= x0;         \
    x0 += x1; x1 = rotl32c(x1, r3); x1 ^= x0;
    TF_G(13, 15, 26, 6)   x0 += k1;  x1 += ks2 + 1u;
    TF_G(17, 29, 16, 24)  x0 += ks2; x1 += k0 + 2u;
    TF_G(13, 15, 26, 6)   x0 += k0;  x1 += k1 + 3u;
    TF_G(17, 29, 16, 24)  x0 += k1;  x1 += ks2 + 4u;
    TF_G(13, 15, 26, 6)   x0 += ks2; x1 += k0 + 5u;
#undef TF_G
    o0 = x0; o1 = x1;
}

constexpr PermTab make_perm_tab() {
    PermTab t{};
    uint32_t sk0 = 0, sk1 = 0;
    tfryc(0u, 42u, 0u, 1u, sk0, sk1);

    unsigned long long keys[1024] = {};
    for (uint32_t i = 0; i < 1024u; i++) {
        uint32_t b0 = 0, b1 = 0;
        tfryc(sk0, sk1, 0u, i, b0, b1);
        keys[i] = ((unsigned long long)(b0 ^ b1) << 32) | (unsigned long long)i;
    }

    const int gaps[8] = {701, 301, 132, 57, 23, 10, 4, 1};
    for (int g = 0; g < 8; g++) {
        int gap = gaps[g];
        for (int i = gap; i < 1024; i++) {
            unsigned long long tmp = keys[i];
            int j = i;
            while (j >= gap && keys[j - gap] > tmp) {
                keys[j] = keys[j - gap];
                j -= gap;
            }
            keys[j] = tmp;
        }
    }

    for (int i = 0; i < 1024; i++) t.v[i] = -1;
    for (int p = 0; p < 256; p++) {
        int col = (int)(keys[p] & 0xFFFFFFFFull);
        t.v[col] = (short)p;
    }
    return t;
}

__device__ const PermTab g_tab = make_perm_tab();

// ---------------------------------------------------------------------------
// Packed fp32x2 helpers (sm_100+): 2 fp32 lanes per instruction, fma pipe.
// ---------------------------------------------------------------------------

union F2U { float2 f; unsigned long long u; };

__device__ __forceinline__ float2 f2add(float2 a, float2 b) {
    F2U A, B, D; A.f = a; B.f = b;
    asm("add.rn.f32x2 %0, %1, %2;" : "=l"(D.u) : "l"(A.u), "l"(B.u));
    return D.f;
}
__device__ __forceinline__ float2 f2mul(float2 a, float2 b) {
    F2U A, B, D; A.f = a; B.f = b;
    asm("mul.rn.f32x2 %0, %1, %2;" : "=l"(D.u) : "l"(A.u), "l"(B.u));
    return D.f;
}
__device__ __forceinline__ float2 f2fma(float2 a, float2 b, float2 c) {
    F2U A, B, C, D; A.f = a; B.f = b; C.f = c;
    asm("fma.rn.f32x2 %0, %1, %2, %3;" : "=l"(D.u) : "l"(A.u), "l"(B.u), "l"(C.u));
    return D.f;
}

// ---------------------------------------------------------------------------
// Persistent LRF kernel: grid-stride over rows; each iteration PREFETCHES the
// next row's 6 float4 (+x0) into registers while phases 1-4 run on the
// current row — after the prologue no warp stalls on DRAM latency.
// Phase code identical to R13 (best measured).
// ---------------------------------------------------------------------------

__global__ void __launch_bounds__(128, 6) lrf_kernel(
    const float* __restrict__ x0,
    const float* __restrict__ x0i,
    float* __restrict__ out,
    int B)
{
    const int t = threadIdx.x;
    const int w = t >> 5;
    const int lane = t & 31;
    const int GS = gridDim.x;
    const int c0 = t * 8;

    __shared__ __align__(16) float redf[32][8];
    __shared__ __align__(16) float redv[32][8];
    __shared__ __align__(16) float4 sbcv[4];
    __shared__ __align__(16) float4 samp[256];

    int b = blockIdx.x;
    if (b >= B) return;

    // ----- prologue: load row b -----
    const float* base = x0i + (size_t)b * 3072 + c0;
    float4 rxa = *reinterpret_cast<const float4*>(base);
    float4 rxb = *reinterpret_cast<const float4*>(base + 4);
    float4 rya = *reinterpret_cast<const float4*>(base + 1024);
    float4 ryb = *reinterpret_cast<const float4*>(base + 1024 + 4);
    float4 rza = *reinterpret_cast<const float4*>(base + 2048);
    float4 rzb = *reinterpret_cast<const float4*>(base + 2048 + 4);
    float px = __ldg(&x0[3 * b + 0]);
    float py = __ldg(&x0[3 * b + 1]);
    float pz = __ldg(&x0[3 * b + 2]);

    for (;;) {
        // ----- deltas for current row (consumes raw regs) -----
        const float2 npx = make_float2(-px, -px);
        const float2 npy = make_float2(-py, -py);
        const float2 npz = make_float2(-pz, -pz);
        float2 X2[4] = { f2add(make_float2(rxa.x, rxa.y), npx),
                         f2add(make_float2(rxa.z, rxa.w), npx),
                         f2add(make_float2(rxb.x, rxb.y), npx),
                         f2add(make_float2(rxb.z, rxb.w), npx) };
        float2 Y2[4] = { f2add(make_float2(rya.x, rya.y), npy),
                         f2add(make_float2(rya.z, rya.w), npy),
                         f2add(make_float2(ryb.x, ryb.y), npy),
                         f2add(make_float2(ryb.z, ryb.w), npy) };
        float2 Z2[4] = { f2add(make_float2(rza.x, rza.y), npz),
                         f2add(make_float2(rza.z, rza.w), npz),
                         f2add(make_float2(rzb.x, rzb.y), npz),
                         f2add(make_float2(rzb.z, rzb.w), npz) };

        // ----- prefetch next row (overlaps all phases below) -----
        const int bn = b + GS;
        const bool more = (bn < B);
        float pxn = 0.f, pyn = 0.f, pzn = 0.f;
        if (more) {
            const float* nb = x0i + (size_t)bn * 3072 + c0;
            rxa = *reinterpret_cast<const float4*>(nb);
            rxb = *reinterpret_cast<const float4*>(nb + 4);
            rya = *reinterpret_cast<const float4*>(nb + 1024);
            ryb = *reinterpret_cast<const float4*>(nb + 1024 + 4);
            rza = *reinterpret_cast<const float4*>(nb + 2048);
            rzb = *reinterpret_cast<const float4*>(nb + 2048 + 4);
            pxn = __ldg(&x0[3 * bn + 0]);
            pyn = __ldg(&x0[3 * bn + 1]);
            pzn = __ldg(&x0[3 * bn + 2]);
        }

        __syncthreads();   // B0: samp from previous iteration fully consumed

        // table (L1-hit after first iteration)
        int4 q = __ldg(reinterpret_cast<const int4*>(&g_tab.v[c0]));
        int iv[8];
        iv[0] = (int)(short)(q.x & 0xffff); iv[1] = q.x >> 16;
        iv[2] = (int)(short)(q.y & 0xffff); iv[3] = q.y >> 16;
        iv[4] = (int)(short)(q.z & 0xffff); iv[5] = q.z >> 16;
        iv[6] = (int)(short)(q.w & 0xffff); iv[7] = q.w >> 16;

        // scatter sampled deltas (1 STS.128 per sample)
#pragma unroll
        for (int k = 0; k < 8; k++) {
            int s = iv[k];
            if (s >= 0) {
                int j = k >> 1;
                if (k & 1) samp[s] = make_float4(X2[j].y, Y2[j].y, Z2[j].y, 0.f);
                else       samp[s] = make_float4(X2[j].x, Y2[j].x, Z2[j].x, 0.f);
            }
        }

        // ----- phase 1: covariance (6) packed; S kept for phase 3 -----
        float2 a00 = {0.f, 0.f}, a01 = a00, a02 = a00, a11 = a00, a12 = a00, a22 = a00;
        float2 s0p = a00, s1p = a00, s2p = a00;
#pragma unroll
        for (int j = 0; j < 4; j++) {
            float2 x = X2[j], y = Y2[j], z = Z2[j];
            a00 = f2fma(x, x, a00); a01 = f2fma(x, y, a01); a02 = f2fma(x, z, a02);
            a11 = f2fma(y, y, a11); a12 = f2fma(y, z, a12); a22 = f2fma(z, z, a22);
            s0p = f2add(s0p, x); s1p = f2add(s1p, y); s2p = f2add(s2p, z);
        }
        float r0 = a00.x + a00.y, r1 = a01.x + a01.y, r2 = a02.x + a02.y;
        float r3 = a11.x + a11.y, r4 = a12.x + a12.y, r5 = a22.x + a22.y;
        const float ss0 = s0p.x + s0p.y;
        const float ss1 = s1p.x + s1p.y;
        const float ss2 = s2p.x + s2p.y;
#pragma unroll
        for (int o = 16; o >= 8; o >>= 1) {
            r0 += __shfl_down_sync(0xffffffffu, r0, o);
            r1 += __shfl_down_sync(0xffffffffu, r1, o);
            r2 += __shfl_down_sync(0xffffffffu, r2, o);
            r3 += __shfl_down_sync(0xffffffffu, r3, o);
            r4 += __shfl_down_sync(0xffffffffu, r4, o);
            r5 += __shfl_down_sync(0xffffffffu, r5, o);
        }
        if (lane < 8) {
            const int row = w * 8 + lane;
            *reinterpret_cast<float4*>(&redf[row][0]) = make_float4(r0, r1, r2, r3);
            *reinterpret_cast<float2*>(&redf[row][4]) = make_float2(r4, r5);
        }
        __syncthreads();   // B1

        // ----- phase 2: eigensolve in warp 0 (unsigned z; sign deferred) -----
        float w0_zx = 0.f, w0_zy = 0.f, w0_zz = 1.f;
        if (w == 0) {
            float sj = 0.f;
            if (lane < 6) {
#pragma unroll
                for (int i = 0; i < 32; i++) sj += redf[i][lane];
            }
            const float invC = 1.0f / 1024.0f;
            const float M00 = __shfl_sync(0xffffffffu, sj, 0) * invC;
            const float M01 = __shfl_sync(0xffffffffu, sj, 1) * invC;
            const float M02 = __shfl_sync(0xffffffffu, sj, 2) * invC;
            const float M11 = __shfl_sync(0xffffffffu, sj, 3) * invC;
            const float M12 = __shfl_sync(0xffffffffu, sj, 4) * invC;
            const float M22 = __shfl_sync(0xffffffffu, sj, 5) * invC;

            float q3 = (M00 + M11 + M22) * (1.0f / 3.0f);
            float d00 = M00 - q3, d11 = M11 - q3, d22 = M22 - q3;
            float p2 = d00 * d00 + d11 * d11 + d22 * d22
                     + 2.0f * (M01 * M01 + M02 * M02 + M12 * M12);
            float p = sqrtf(p2 * (1.0f / 6.0f));
            float zx, zy, zz;
            if (p < 1e-18f) {
                zx = 0.f; zy = 0.f; zz = 1.f;
            } else {
                float ip = 1.0f / p;
                float c00 = d00 * ip, c11 = d11 * ip, c22 = d22 * ip;
                float c01 = M01 * ip, c02 = M02 * ip, c12 = M12 * ip;
                float det = c00 * (c11 * c22 - c12 * c12)
                          - c01 * (c01 * c22 - c12 * c02)
                          + c02 * (c01 * c12 - c11 * c02);
                float r = fminf(1.0f, fmaxf(-1.0f, 0.5f * det));
                float phi = acosf(r) * (1.0f / 3.0f);
                float lmax = q3 + 2.0f * p * cosf(phi);

                float m00 = M00 - lmax, m11 = M11 - lmax, m22 = M22 - lmax;
                float cx0 = M01 * M12 - M02 * m11;
                float cy0 = M02 * M01 - m00 * M12;
                float cz0 = m00 * m11 - M01 * M01;
                float cx1 = M01 * m22 - M02 * M12;
                float cy1 = M02 * M02 - m00 * m22;
                float cz1 = m00 * M12 - M01 * M02;
                float cx2 = m11 * m22 - M12 * M12;
                float cy2 = M12 * M02 - M01 * m22;
                float cz2 = M01 * M12 - m11 * M02;
                float n0 = cx0 * cx0 + cy0 * cy0 + cz0 * cz0;
                float n1 = cx1 * cx1 + cy1 * cy1 + cz1 * cz1;
                float n2 = cx2 * cx2 + cy2 * cy2 + cz2 * cz2;
                float ex, ey, ez, nn;
                if (n0 >= n1 && n0 >= n2)      { ex = cx0; ey = cy0; ez = cz0; nn = n0; }
                else if (n1 >= n2)             { ex = cx1; ey = cy1; ez = cz1; nn = n1; }
                else                           { ex = cx2; ey = cy2; ez = cz2; nn = n2; }
                if (nn < 1e-30f) { ex = 1.f; ey = 0.f; ez = 0.f; nn = 1.f; }
                float einv = rsqrtf(nn);
                ex *= einv; ey *= einv; ez *= einv;

                float uxx, uxy, uxz;
                float aex = fabsf(ex), aey = fabsf(ey), aez = fabsf(ez);
                if (aex <= aey && aex <= aez)      { uxx = 0.f; uxy = -ez; uxz =  ey; }
                else if (aey <= aez)               { uxx =  ez; uxy = 0.f; uxz = -ex; }
                else                               { uxx = -ey; uxy =  ex; uxz = 0.f; }
                float uinv = rsqrtf(uxx * uxx + uxy * uxy + uxz * uxz);
                uxx *= uinv; uxy *= uinv; uxz *= uinv;
                float vxx = ey * uxz - ez * uxy;
                float vxy = ez * uxx - ex * uxz;
                float vxz = ex * uxy - ey * uxx;

                float Mux = fmaf(M00, uxx, fmaf(M01, uxy, M02 * uxz));
                float Muy = fmaf(M01, uxx, fmaf(M11, uxy, M12 * uxz));
                float Muz = fmaf(M02, uxx, fmaf(M12, uxy, M22 * uxz));
                float Mvx = fmaf(M00, vxx, fmaf(M01, vxy, M02 * vxz));
                float Mvy = fmaf(M01, vxx, fmaf(M11, vxy, M12 * vxz));
                float Mvz = fmaf(M02, vxx, fmaf(M12, vxy, M22 * vxz));
                float b00 = fmaf(uxx, Mux, fmaf(uxy, Muy, uxz * Muz));
                float b01 = fmaf(uxx, Mvx, fmaf(uxy, Mvy, uxz * Mvz));
                float b11 = fmaf(vxx, Mvx, fmaf(vxy, Mvy, vxz * Mvz));

                float half = 0.5f * (b00 - b11);
                float rt = sqrtf(fmaf(half, half, b01 * b01));
                float cc, ss;
                if (half >= 0.f) { cc = b01;       ss = -(half + rt); }
                else             { cc = rt - half; ss = -b01; }
                float cn2 = fmaf(cc, cc, ss * ss);
                if (cn2 < 1e-30f) { cc = 1.f; ss = 0.f; cn2 = 1.f; }
                float cninv = rsqrtf(cn2);
                cc *= cninv; ss *= cninv;

                zx = fmaf(cc, uxx, ss * vxx);
                zy = fmaf(cc, uxy, ss * vxy);
                zz = fmaf(cc, uxz, ss * vxz);
            }
            w0_zx = zx; w0_zy = zy; w0_zz = zz;
            if (lane == 0) sbcv[0] = make_float4(zx, zy, zz, 0.f);
        }
        __syncthreads();   // B2

        const float4 zv = sbcv[0];
        const float2 zx2 = make_float2(zv.x, zv.x);
        const float2 zy2 = make_float2(zv.y, zv.y);
        const float2 zz2 = make_float2(zv.z, zv.z);
        const float2 neg1 = make_float2(-1.f, -1.f);

        // ----- phase 3: vi_c accumulation (sign-invariant in z) -----
        float2 v0p = {0.f, 0.f}, v1p = v0p, v2p = v0p;
#pragma unroll
        for (int j = 0; j < 4; j++) {
            float2 x = X2[j], y = Y2[j], z = Z2[j];
            float2 nrm = f2fma(zx2, x, f2fma(zy2, y, f2mul(zz2, z)));
            float2 d2  = f2fma(x, x, f2fma(y, y, f2mul(z, z)));
            float2 am  = make_float2(1.0f - sqrtf(d2.x), 1.0f - sqrtf(d2.y));
            float2 coef = f2mul(f2mul(am, am), f2mul(nrm, nrm));
            float2 nn = f2mul(nrm, neg1);
            v0p = f2fma(coef, f2fma(nn, zx2, x), v0p);
            v1p = f2fma(coef, f2fma(nn, zy2, y), v1p);
            v2p = f2fma(coef, f2fma(nn, zz2, z), v2p);
        }
        float v0 = v0p.x + v0p.y, v1 = v1p.x + v1p.y, v2 = v2p.x + v2p.y;
        float u0 = ss0, u1 = ss1, u2 = ss2;
#pragma unroll
        for (int o = 16; o >= 8; o >>= 1) {
            v0 += __shfl_down_sync(0xffffffffu, v0, o);
            v1 += __shfl_down_sync(0xffffffffu, v1, o);
            v2 += __shfl_down_sync(0xffffffffu, v2, o);
            u0 += __shfl_down_sync(0xffffffffu, u0, o);
            u1 += __shfl_down_sync(0xffffffffu, u1, o);
            u2 += __shfl_down_sync(0xffffffffu, u2, o);
        }
        if (lane < 8) {
            const int row = w * 8 + lane;
            *reinterpret_cast<float4*>(&redv[row][0]) = make_float4(v0, v1, v2, u0);
            *reinterpret_cast<float2*>(&redv[row][4]) = make_float2(u1, u2);
        }
        __syncthreads();   // B3

        // ----- warp 0: combine, sign, frame; broadcast via sbcv -----
        if (w == 0) {
            float sj = 0.f;
            if (lane < 6) {
#pragma unroll
                for (int i = 0; i < 32; i++) sj += redv[i][lane];
            }
            const float c0f = __shfl_sync(0xffffffffu, sj, 0);
            const float c1f = __shfl_sync(0xffffffffu, sj, 1);
            const float c2f = __shfl_sync(0xffffffffu, sj, 2);
            const float S0  = __shfl_sync(0xffffffffu, sj, 3);
            const float S1  = __shfl_sync(0xffffffffu, sj, 4);
            const float S2  = __shfl_sync(0xffffffffu, sj, 5);

            float sgn = (-(w0_zx * S0 + w0_zy * S1 + w0_zz * S2) < 0.f) ? -1.f : 1.f;
            float zpx = w0_zx * sgn, zpy = w0_zy * sgn, zpz = w0_zz * sgn;

            float nrm2 = fmaf(c0f, c0f, fmaf(c1f, c1f, c2f * c2f));
            float invn = rsqrtf(nrm2);
            float ax = c0f * invn, ay = c1f * invn, az = c2f * invn;
            float yx = ay * zpz - az * zpy;
            float yy = az * zpx - ax * zpz;
            float yz = ax * zpy - ay * zpx;

            if (lane == 0) {
                sbcv[1] = make_float4(ax, ay, az, 0.f);
                sbcv[2] = make_float4(yx, yy, yz, 0.f);
                sbcv[3] = make_float4(zpx, zpy, zpz, 0.f);
            }
        }
        __syncthreads();   // B4

        // ----- phase 4: project 2 sampled columns per thread -----
        const float4 fa = sbcv[1];
        const float4 fy = sbcv[2];
        const float4 fz = sbcv[3];

        const int s0i = 2 * t;
        float4 va = samp[s0i];
        float4 vb = samp[s0i + 1];
        float2 vx2 = make_float2(va.x, vb.x);
        float2 vy2 = make_float2(va.y, vb.y);
        float2 vz2 = make_float2(va.z, vb.z);

        float2 ax2 = make_float2(fa.x, fa.x), ay2 = make_float2(fa.y, fa.y), az2 = make_float2(fa.z, fa.z);
        float2 yx2 = make_float2(fy.x, fy.x), yy2 = make_float2(fy.y, fy.y), yz2 = make_float2(fy.z, fy.z);
        float2 zpx2 = make_float2(fz.x, fz.x), zpy2 = make_float2(fz.y, fz.y), zpz2 = make_float2(fz.z, fz.z);

        float2 o0 = f2fma(ax2, vx2, f2fma(ay2, vy2, f2mul(az2, vz2)));
        float2 o1 = f2fma(yx2, vx2, f2fma(yy2, vy2, f2mul(yz2, vz2)));
        float2 o2 = f2fma(zpx2, vx2, f2fma(zpy2, vy2, f2mul(zpz2, vz2)));

        float* ob = out + (size_t)b * 768 + s0i;
        *reinterpret_cast<float2*>(ob)       = o0;
        *reinterpret_cast<float2*>(ob + 256) = o1;
        *reinterpret_cast<float2*>(ob + 512) = o2;

        if (!more) break;
        b = bn;
        px = pxn; py = pyn; pz = pzn;
    }
}

// ---------------------------------------------------------------------------

extern "C" void kernel_launch(void* const* d_in, const int* in_sizes, int n_in,
                              void* d_out, int out_size) {
    const float* x0  = (const float*)d_in[0];
    const float* x0i = (const float*)d_in[1];
    if (n_in >= 2 && in_sizes[0] > in_sizes[1]) {
        const float* tmp = x0; x0 = x0i; x0i = tmp;
    }
    int B;
    if (in_sizes[0] <= in_sizes[1]) B = in_sizes[0] / 3;
    else                            B = in_sizes[1] / 3;

    float* out = (float*)d_out;

    int grid = 148 * 6;           // persistent: 6 blocks/SM x 148 SMs
    if (grid > B) grid = B;

    lrf_kernel<<<grid, 128>>>(x0, x0i, out, B);
}

// round 15
// speedup vs baseline: 1.1289x; 1.1289x over previous
#include <cuda_runtime.h>
#include <stdint.h>
#include <math.h>

// ---------------------------------------------------------------------------
// Permutation jax.random.permutation(key(42), 1024)[:256] — evaluated at
// COMPILE TIME (constexpr threefry2x32 + stable shell sort), baked into a
// __device__ const global table, read via vectorized LDG (global->L1).
// g_tab.v[col] = sample slot (0..255) or -1, packed int16 (2KB).
// ---------------------------------------------------------------------------

struct __align__(16) PermTab { short v[1024]; };

constexpr uint32_t rotl32c(uint32_t x, int r) {
    return (x << r) | (x >> (32 - r));
}

constexpr void tfryc(uint32_t k0, uint32_t k1, uint32_t c0, uint32_t c1,
                     uint32_t& o0, uint32_t& o1) {
    uint32_t ks2 = k0 ^ k1 ^ 0x1BD11BDAu;
    uint32_t x0 = c0 + k0;
    uint32_t x1 = c1 + k1;
#define TF_G(r0, r1, r2, r3)                          \
    x0 += x1; x1 = rotl32c(x1, r0); x1 ^= x0;         \
    x0 += x1; x1 = rotl32c(x1, r1); x1 ^= x0;         \
    x0 += x1; x1 = rotl32c(x1, r2); x1 ^= x0;         \
    x0 += x1; x1 = rotl32c(x1, r3); x1 ^= x0;
    TF_G(13, 15, 26, 6)   x0 += k1;  x1 += ks2 + 1u;
    TF_G(17, 29, 16, 24)  x0 += ks2; x1 += k0 + 2u;
    TF_G(13, 15, 26, 6)   x0 += k0;  x1 += k1 + 3u;
    TF_G(17, 29, 16, 24)  x0 += k1;  x1 += ks2 + 4u;
    TF_G(13, 15, 26, 6)   x0 += ks2; x1 += k0 + 5u;
#undef TF_G
    o0 = x0; o1 = x1;
}

constexpr PermTab make_perm_tab() {
    PermTab t{};
    uint32_t sk0 = 0, sk1 = 0;
    tfryc(0u, 42u, 0u, 1u, sk0, sk1);

    unsigned long long keys[1024] = {};
    for (uint32_t i = 0; i < 1024u; i++) {
        uint32_t b0 = 0, b1 = 0;
        tfryc(sk0, sk1, 0u, i, b0, b1);
        keys[i] = ((unsigned long long)(b0 ^ b1) << 32) | (unsigned long long)i;
    }

    const int gaps[8] = {701, 301, 132, 57, 23, 10, 4, 1};
    for (int g = 0; g < 8; g++) {
        int gap = gaps[g];
        for (int i = gap; i < 1024; i++) {
            unsigned long long tmp = keys[i];
            int j = i;
            while (j >= gap && keys[j - gap] > tmp) {
                keys[j] = keys[j - gap];
                j -= gap;
            }
            keys[j] = tmp;
        }
    }

    for (int i = 0; i < 1024; i++) t.v[i] = -1;
    for (int p = 0; p < 256; p++) {
        int col = (int)(keys[p] & 0xFFFFFFFFull);
        t.v[col] = (short)p;
    }
    return t;
}

__device__ const PermTab g_tab = make_perm_tab();

// ---------------------------------------------------------------------------
// Packed fp32x2 helpers (sm_100+): 2 fp32 lanes per instruction, fma pipe.
// ---------------------------------------------------------------------------

union F2U { float2 f; unsigned long long u; };

__device__ __forceinline__ float2 f2add(float2 a, float2 b) {
    F2U A, B, D; A.f = a; B.f = b;
    asm("add.rn.f32x2 %0, %1, %2;" : "=l"(D.u) : "l"(A.u), "l"(B.u));
    return D.f;
}
__device__ __forceinline__ float2 f2mul(float2 a, float2 b) {
    F2U A, B, D; A.f = a; B.f = b;
    asm("mul.rn.f32x2 %0, %1, %2;" : "=l"(D.u) : "l"(A.u), "l"(B.u));
    return D.f;
}
__device__ __forceinline__ float2 f2fma(float2 a, float2 b, float2 c) {
    F2U A, B, C, D; A.f = a; B.f = b; C.f = c;
    asm("fma.rn.f32x2 %0, %1, %2, %3;" : "=l"(D.u) : "l"(A.u), "l"(B.u), "l"(C.u));
    return D.f;
}

// ---------------------------------------------------------------------------
// Main LRF kernel (R13 structure): one block of 128 threads per batch row,
// 8 cols/thread as 4 f32x2 pairs, deltas in registers, sign deferred.
// R15: __launch_bounds__(128, 10) (51-reg target -> 10 blocks/SM) + MUFU cos
// in the warp-0 eigensolve (shorter serial path, lower reg high-water mark).
// ---------------------------------------------------------------------------

__global__ void __launch_bounds__(128, 10) lrf_kernel(
    const float* __restrict__ x0,
    const float* __restrict__ x0i,
    float* __restrict__ out)
{
    const int b = blockIdx.x;
    const int t = threadIdx.x;
    const int w = t >> 5;
    const int lane = t & 31;

    __shared__ __align__(16) float redf[32][8];  // cov partials (6 used)
    __shared__ __align__(16) float redv[32][8];  // vi+S partials (6 used)
    __shared__ __align__(16) float4 sbcv[4];     // [0]=z, [1]=xp_ax, [2]=yp, [3]=zp
    __shared__ __align__(16) float4 samp[256];   // (x, y, z, pad) per sample

    const float px = __ldg(&x0[3 * b + 0]);
    const float py = __ldg(&x0[3 * b + 1]);
    const float pz = __ldg(&x0[3 * b + 2]);
    const float2 npx = make_float2(-px, -px);
    const float2 npy = make_float2(-py, -py);
    const float2 npz = make_float2(-pz, -pz);

    const float* base = x0i + (size_t)b * 3072;
    const int c0 = t * 8;

    float4 xa = *reinterpret_cast<const float4*>(base + c0);
    float4 xb = *reinterpret_cast<const float4*>(base + c0 + 4);
    float4 ya = *reinterpret_cast<const float4*>(base + 1024 + c0);
    float4 yb = *reinterpret_cast<const float4*>(base + 1024 + c0 + 4);
    float4 za = *reinterpret_cast<const float4*>(base + 2048 + c0);
    float4 zb = *reinterpret_cast<const float4*>(base + 2048 + c0 + 4);
    int4 q = __ldg(reinterpret_cast<const int4*>(&g_tab.v[c0]));  // 8 shorts

    float2 X2[4] = { f2add(make_float2(xa.x, xa.y), npx),
                     f2add(make_float2(xa.z, xa.w), npx),
                     f2add(make_float2(xb.x, xb.y), npx),
                     f2add(make_float2(xb.z, xb.w), npx) };
    float2 Y2[4] = { f2add(make_float2(ya.x, ya.y), npy),
                     f2add(make_float2(ya.z, ya.w), npy),
                     f2add(make_float2(yb.x, yb.y), npy),
                     f2add(make_float2(yb.z, yb.w), npy) };
    float2 Z2[4] = { f2add(make_float2(za.x, za.y), npz),
                     f2add(make_float2(za.z, za.w), npz),
                     f2add(make_float2(zb.x, zb.y), npz),
                     f2add(make_float2(zb.z, zb.w), npz) };

    // unpack 8 int16 slots (sign-extended)
    int iv[8];
    iv[0] = (int)(short)(q.x & 0xffff); iv[1] = q.x >> 16;
    iv[2] = (int)(short)(q.y & 0xffff); iv[3] = q.y >> 16;
    iv[4] = (int)(short)(q.z & 0xffff); iv[5] = q.z >> 16;
    iv[6] = (int)(short)(q.w & 0xffff); iv[7] = q.w >> 16;

    // scatter sampled deltas into packed smem slots (1 STS.128 per sample)
#pragma unroll
    for (int k = 0; k < 8; k++) {
        int s = iv[k];
        if (s >= 0) {
            int j = k >> 1;
            if (k & 1) samp[s] = make_float4(X2[j].y, Y2[j].y, Z2[j].y, 0.f);
            else       samp[s] = make_float4(X2[j].x, Y2[j].x, Z2[j].x, 0.f);
        }
    }

    // ----- phase 1: covariance (6) packed; column sum stays for phase 3 -----
    float2 a00 = {0.f, 0.f}, a01 = a00, a02 = a00, a11 = a00, a12 = a00, a22 = a00;
    float2 s0p = a00, s1p = a00, s2p = a00;
#pragma unroll
    for (int j = 0; j < 4; j++) {
        float2 x = X2[j], y = Y2[j], z = Z2[j];
        a00 = f2fma(x, x, a00); a01 = f2fma(x, y, a01); a02 = f2fma(x, z, a02);
        a11 = f2fma(y, y, a11); a12 = f2fma(y, z, a12); a22 = f2fma(z, z, a22);
        s0p = f2add(s0p, x); s1p = f2add(s1p, y); s2p = f2add(s2p, z);
    }
    float r0 = a00.x + a00.y, r1 = a01.x + a01.y, r2 = a02.x + a02.y;
    float r3 = a11.x + a11.y, r4 = a12.x + a12.y, r5 = a22.x + a22.y;
    const float ss0 = s0p.x + s0p.y;
    const float ss1 = s1p.x + s1p.y;
    const float ss2 = s2p.x + s2p.y;
    // 2-level tree: 12 SHFL/warp; lanes 0-7 hold partials
#pragma unroll
    for (int o = 16; o >= 8; o >>= 1) {
        r0 += __shfl_down_sync(0xffffffffu, r0, o);
        r1 += __shfl_down_sync(0xffffffffu, r1, o);
        r2 += __shfl_down_sync(0xffffffffu, r2, o);
        r3 += __shfl_down_sync(0xffffffffu, r3, o);
        r4 += __shfl_down_sync(0xffffffffu, r4, o);
        r5 += __shfl_down_sync(0xffffffffu, r5, o);
    }
    if (lane < 8) {
        const int row = w * 8 + lane;
        *reinterpret_cast<float4*>(&redf[row][0]) = make_float4(r0, r1, r2, r3);
        *reinterpret_cast<float2*>(&redf[row][4]) = make_float2(r4, r5);
    }
    __syncthreads();   // B1

    // ----- phase 2: eigensolve in warp 0 (UNSIGNED z; sign deferred) -----
    float w0_zx = 0.f, w0_zy = 0.f, w0_zz = 1.f;
    if (w == 0) {
        float sj = 0.f;
        if (lane < 6) {
#pragma unroll
            for (int i = 0; i < 32; i++) sj += redf[i][lane];
        }
        const float invC = 1.0f / 1024.0f;
        const float M00 = __shfl_sync(0xffffffffu, sj, 0) * invC;
        const float M01 = __shfl_sync(0xffffffffu, sj, 1) * invC;
        const float M02 = __shfl_sync(0xffffffffu, sj, 2) * invC;
        const float M11 = __shfl_sync(0xffffffffu, sj, 3) * invC;
        const float M12 = __shfl_sync(0xffffffffu, sj, 4) * invC;
        const float M22 = __shfl_sync(0xffffffffu, sj, 5) * invC;

        // (a) largest eigenvalue via trig formula (well-conditioned at r->1)
        float q3 = (M00 + M11 + M22) * (1.0f / 3.0f);
        float d00 = M00 - q3, d11 = M11 - q3, d22 = M22 - q3;
        float p2 = d00 * d00 + d11 * d11 + d22 * d22
                 + 2.0f * (M01 * M01 + M02 * M02 + M12 * M12);
        float p = sqrtf(p2 * (1.0f / 6.0f));
        float zx, zy, zz;
        if (p < 1e-18f) {
            zx = 0.f; zy = 0.f; zz = 1.f;
        } else {
            float ip = 1.0f / p;
            float c00 = d00 * ip, c11 = d11 * ip, c22 = d22 * ip;
            float c01 = M01 * ip, c02 = M02 * ip, c12 = M12 * ip;
            float det = c00 * (c11 * c22 - c12 * c12)
                      - c01 * (c01 * c22 - c12 * c02)
                      + c02 * (c01 * c12 - c11 * c02);
            float r = fminf(1.0f, fmaxf(-1.0f, 0.5f * det));
            float phi = acosf(r) * (1.0f / 3.0f);
            float lmax = q3 + 2.0f * p * __cosf(phi);   // MUFU cos: eps~2^-21 ok

            // (b) eigenvector e1 of lmax via row cross-products
            float m00 = M00 - lmax, m11 = M11 - lmax, m22 = M22 - lmax;
            float cx0 = M01 * M12 - M02 * m11;
            float cy0 = M02 * M01 - m00 * M12;
            float cz0 = m00 * m11 - M01 * M01;
            float cx1 = M01 * m22 - M02 * M12;
            float cy1 = M02 * M02 - m00 * m22;
            float cz1 = m00 * M12 - M01 * M02;
            float cx2 = m11 * m22 - M12 * M12;
            float cy2 = M12 * M02 - M01 * m22;
            float cz2 = M01 * M12 - m11 * M02;
            float n0 = cx0 * cx0 + cy0 * cy0 + cz0 * cz0;
            float n1 = cx1 * cx1 + cy1 * cy1 + cz1 * cz1;
            float n2 = cx2 * cx2 + cy2 * cy2 + cz2 * cz2;
            float ex, ey, ez, nn;
            if (n0 >= n1 && n0 >= n2)      { ex = cx0; ey = cy0; ez = cz0; nn = n0; }
            else if (n1 >= n2)             { ex = cx1; ey = cy1; ez = cz1; nn = n1; }
            else                           { ex = cx2; ey = cy2; ez = cz2; nn = n2; }
            if (nn < 1e-30f) { ex = 1.f; ey = 0.f; ez = 0.f; nn = 1.f; }
            float einv = rsqrtf(nn);
            ex *= einv; ey *= einv; ez *= einv;

            // (c) orthonormal basis {u,v} of complement of e1
            float uxx, uxy, uxz;
            float aex = fabsf(ex), aey = fabsf(ey), aez = fabsf(ez);
            if (aex <= aey && aex <= aez)      { uxx = 0.f; uxy = -ez; uxz =  ey; }
            else if (aey <= aez)               { uxx =  ez; uxy = 0.f; uxz = -ex; }
            else                               { uxx = -ey; uxy =  ex; uxz = 0.f; }
            float uinv = rsqrtf(uxx * uxx + uxy * uxy + uxz * uxz);
            uxx *= uinv; uxy *= uinv; uxz *= uinv;
            float vxx = ey * uxz - ez * uxy;
            float vxy = ez * uxx - ex * uxz;
            float vxz = ex * uxy - ey * uxx;

            // (d) 2x2 projected matrix B
            float Mux = fmaf(M00, uxx, fmaf(M01, uxy, M02 * uxz));
            float Muy = fmaf(M01, uxx, fmaf(M11, uxy, M12 * uxz));
            float Muz = fmaf(M02, uxx, fmaf(M12, uxy, M22 * uxz));
            float Mvx = fmaf(M00, vxx, fmaf(M01, vxy, M02 * vxz));
            float Mvy = fmaf(M01, vxx, fmaf(M11, vxy, M12 * vxz));
            float Mvz = fmaf(M02, vxx, fmaf(M12, vxy, M22 * vxz));
            float b00 = fmaf(uxx, Mux, fmaf(uxy, Muy, uxz * Muz));
            float b01 = fmaf(uxx, Mvx, fmaf(uxy, Mvy, uxz * Mvz));
            float b11 = fmaf(vxx, Mvx, fmaf(vxy, Mvy, vxz * Mvz));

            // (e) smallest eigenvector of B (cancellation-free)
            float half = 0.5f * (b00 - b11);
            float rt = sqrtf(fmaf(half, half, b01 * b01));
            float cc, ss;
            if (half >= 0.f) { cc = b01;       ss = -(half + rt); }
            else             { cc = rt - half; ss = -b01; }
            float cn2 = fmaf(cc, cc, ss * ss);
            if (cn2 < 1e-30f) { cc = 1.f; ss = 0.f; cn2 = 1.f; }
            float cninv = rsqrtf(cn2);
            cc *= cninv; ss *= cninv;

            zx = fmaf(cc, uxx, ss * vxx);
            zy = fmaf(cc, uxy, ss * vxy);
            zz = fmaf(cc, uxz, ss * vxz);
        }
        w0_zx = zx; w0_zy = zy; w0_zz = zz;
        if (lane == 0) sbcv[0] = make_float4(zx, zy, zz, 0.f);
    }
    __syncthreads();   // B2

    const float4 zv = sbcv[0];
    const float2 zx2 = make_float2(zv.x, zv.x);
    const float2 zy2 = make_float2(zv.y, zv.y);
    const float2 zz2 = make_float2(zv.z, zv.z);
    const float2 neg1 = make_float2(-1.f, -1.f);

    // ----- phase 3: vi_c accumulation (sign-invariant in z), packed -----
    float2 v0p = {0.f, 0.f}, v1p = v0p, v2p = v0p;
#pragma unroll
    for (int j = 0; j < 4; j++) {
        float2 x = X2[j], y = Y2[j], z = Z2[j];
        float2 nrm = f2fma(zx2, x, f2fma(zy2, y, f2mul(zz2, z)));
        float2 d2  = f2fma(x, x, f2fma(y, y, f2mul(z, z)));
        float2 am  = make_float2(1.0f - sqrtf(d2.x), 1.0f - sqrtf(d2.y));
        float2 coef = f2mul(f2mul(am, am), f2mul(nrm, nrm));
        float2 nn = f2mul(nrm, neg1);
        v0p = f2fma(coef, f2fma(nn, zx2, x), v0p);
        v1p = f2fma(coef, f2fma(nn, zy2, y), v1p);
        v2p = f2fma(coef, f2fma(nn, zz2, z), v2p);
    }
    // reduce 6 values (vi + S), 2-level tree: 12 SHFL/warp
    float v0 = v0p.x + v0p.y, v1 = v1p.x + v1p.y, v2 = v2p.x + v2p.y;
    float u0 = ss0, u1 = ss1, u2 = ss2;
#pragma unroll
    for (int o = 16; o >= 8; o >>= 1) {
        v0 += __shfl_down_sync(0xffffffffu, v0, o);
        v1 += __shfl_down_sync(0xffffffffu, v1, o);
        v2 += __shfl_down_sync(0xffffffffu, v2, o);
        u0 += __shfl_down_sync(0xffffffffu, u0, o);
        u1 += __shfl_down_sync(0xffffffffu, u1, o);
        u2 += __shfl_down_sync(0xffffffffu, u2, o);
    }
    if (lane < 8) {
        const int row = w * 8 + lane;
        *reinterpret_cast<float4*>(&redv[row][0]) = make_float4(v0, v1, v2, u0);
        *reinterpret_cast<float2*>(&redv[row][4]) = make_float2(u1, u2);
    }
    __syncthreads();   // B3

    // ----- warp 0: combine, sign, frame; broadcast via sbcv -----
    if (w == 0) {
        float sj = 0.f;
        if (lane < 6) {
#pragma unroll
            for (int i = 0; i < 32; i++) sj += redv[i][lane];
        }
        const float c0f = __shfl_sync(0xffffffffu, sj, 0);
        const float c1f = __shfl_sync(0xffffffffu, sj, 1);
        const float c2f = __shfl_sync(0xffffffffu, sj, 2);
        const float S0  = __shfl_sync(0xffffffffu, sj, 3);
        const float S1  = __shfl_sync(0xffffffffu, sj, 4);
        const float S2  = __shfl_sync(0xffffffffu, sj, 5);

        // sign: s_ref = z . sum(xp - xpi) = -(z . sum(xs))
        float sgn = (-(w0_zx * S0 + w0_zy * S1 + w0_zz * S2) < 0.f) ? -1.f : 1.f;
        float zpx = w0_zx * sgn, zpy = w0_zy * sgn, zpz = w0_zz * sgn;

        float nrm2 = fmaf(c0f, c0f, fmaf(c1f, c1f, c2f * c2f));
        float invn = rsqrtf(nrm2);
        float ax = c0f * invn, ay = c1f * invn, az = c2f * invn;
        float yx = ay * zpz - az * zpy;
        float yy = az * zpx - ax * zpz;
        float yz = ax * zpy - ay * zpx;

        if (lane == 0) {
            sbcv[1] = make_float4(ax, ay, az, 0.f);
            sbcv[2] = make_float4(yx, yy, yz, 0.f);
            sbcv[3] = make_float4(zpx, zpy, zpz, 0.f);
        }
    }
    __syncthreads();   // B4

    // ----- phase 4: project 2 sampled columns per thread (LDS.128, packed) -----
    const float4 fa = sbcv[1];
    const float4 fy = sbcv[2];
    const float4 fz = sbcv[3];

    const int s0i = 2 * t;
    float4 va = samp[s0i];
    float4 vb = samp[s0i + 1];
    float2 vx2 = make_float2(va.x, vb.x);
    float2 vy2 = make_float2(va.y, vb.y);
    float2 vz2 = make_float2(va.z, vb.z);

    float2 ax2 = make_float2(fa.x, fa.x), ay2 = make_float2(fa.y, fa.y), az2 = make_float2(fa.z, fa.z);
    float2 yx2 = make_float2(fy.x, fy.x), yy2 = make_float2(fy.y, fy.y), yz2 = make_float2(fy.z, fy.z);
    float2 zpx2 = make_float2(fz.x, fz.x), zpy2 = make_float2(fz.y, fz.y), zpz2 = make_float2(fz.z, fz.z);

    float2 o0 = f2fma(ax2, vx2, f2fma(ay2, vy2, f2mul(az2, vz2)));
    float2 o1 = f2fma(yx2, vx2, f2fma(yy2, vy2, f2mul(yz2, vz2)));
    float2 o2 = f2fma(zpx2, vx2, f2fma(zpy2, vy2, f2mul(zpz2, vz2)));

    float* ob = out + (size_t)b * 768 + s0i;
    *reinterpret_cast<float2*>(ob)       = o0;
    *reinterpret_cast<float2*>(ob + 256) = o1;
    *reinterpret_cast<float2*>(ob + 512) = o2;
}

// ---------------------------------------------------------------------------

extern "C" void kernel_launch(void* const* d_in, const int* in_sizes, int n_in,
                              void* d_out, int out_size) {
    const float* x0  = (const float*)d_in[0];
    const float* x0i = (const float*)d_in[1];
    if (n_in >= 2 && in_sizes[0] > in_sizes[1]) {
        const float* tmp = x0; x0 = x0i; x0i = tmp;
    }
    int B;
    if (in_sizes[0] <= in_sizes[1]) B = in_sizes[0] / 3;
    else                            B = in_sizes[1] / 3;

    float* out = (float*)d_out;

    lrf_kernel<<<B, 128>>>(x0, x0i, out);
}